// round 15
// baseline (speedup 1.0000x reference)
#include <cuda_runtime.h>
#include <cuda_fp16.h>
#include <cstdint>

#define N_NODES 50000
#define N_EDGES 800000
#define HDIM 128
#define DDIM 32
#define CDIM 64
#define RDIM 8

#define TILES_C 6250            // ceil(400000/64)
#define TILES_N 782             // ceil(50000/64)
#define NB_C 366
#define NB_N 78                 // 444 = 3 blocks/SM; node tile ~1.7x coeffs tile

// ---- scratch (device globals; no allocation in kernel_launch) ----
__device__ float g_hbuf[N_NODES * DDIM];        // h          [N,32]
__device__ float g_cbuf[N_NODES * RDIM * DDIM]; // c          [N*R,32]
__device__ float g_agg[N_NODES * DDIM];         // segsum     [N,32]
__device__ int   g_cnt[N_NODES];                // src histogram
__device__ int   g_off[N_NODES];                // exclusive offsets (consumed by scatter)
__device__ int   g_src_s[N_EDGES];              // src, sorted by src
__device__ int   g_dst_s[N_EDGES];              // dst, sorted by src
__device__ int   g_perm[N_EDGES];               // original edge id, sorted by src

__device__ __forceinline__ float silu_f(float v) {
    return __fdividef(v, 1.0f + __expf(-v));
}

__device__ __forceinline__ uint32_t packh2(float lo, float hi) {
    uint32_t r;
    asm("cvt.rn.f16x2.f32 %0, %1, %2;" : "=r"(r) : "f"(hi), "f"(lo));
    return r;
}

__device__ __forceinline__ void mma_f16(float d[4], uint32_t a0, uint32_t a1,
                                        uint32_t a2, uint32_t a3,
                                        uint32_t b0, uint32_t b1) {
    asm volatile(
        "mma.sync.aligned.m16n8k16.row.col.f32.f16.f16.f32 "
        "{%0,%1,%2,%3},{%4,%5,%6,%7},{%8,%9},{%0,%1,%2,%3};"
        : "+f"(d[0]), "+f"(d[1]), "+f"(d[2]), "+f"(d[3])
        : "r"(a0), "r"(a1), "r"(a2), "r"(a3), "r"(b0), "r"(b1));
}

__device__ __forceinline__ void red_v4(float* p, float4 v) {
    asm volatile("red.global.add.v4.f32 [%0], {%1,%2,%3,%4};"
                 :: "l"(p), "f"(v.x), "f"(v.y), "f"(v.z), "f"(v.w) : "memory");
}

// Fused 2-layer MLP (fp16 tensor-core) — unchanged from R14.
template<int K, bool BIAS>
__device__ void mlp_tiles(const float* __restrict__ A, const float* __restrict__ W1,
                          const float* __restrict__ b1, const float* __restrict__ W2,
                          const float* __restrict__ b2, float* __restrict__ Y,
                          int M, int t0, int t1, uint32_t* sm)
{
    constexpr int R1 = K / 4;
    uint2* W1p = (uint2*)sm;                    // [R1][132]
    uint2* W2p = W1p + R1 * 132;                // [32][36]
    uint32_t* C1h = (uint32_t*)(W2p + 32 * 36); // [64][68]
    float* b1s = (float*)(C1h + 64 * 68);       // [128]
    float* b2s = b1s + 128;                     // [32]

    const int tid = threadIdx.x;

    for (int i = tid; i < R1 * 128; i += 256) {
        int r = i >> 7, col = i & 127;
        int kg = r >> 2, tg = r & 3;
        int k0 = kg * 16 + 2 * tg;
        float w00 = W1[(size_t)k0 * 128 + col];
        float w01 = W1[(size_t)(k0 + 1) * 128 + col];
        float w10 = W1[(size_t)(k0 + 8) * 128 + col];
        float w11 = W1[(size_t)(k0 + 9) * 128 + col];
        W1p[r * 132 + col] = make_uint2(packh2(w00, w01), packh2(w10, w11));
    }
    for (int i = tid; i < 32 * 32; i += 256) {
        int r = i >> 5, n = i & 31;
        int kg = r >> 2, tg = r & 3;
        int k0 = kg * 16 + 2 * tg;
        float w00 = W2[(size_t)k0 * 32 + n];
        float w01 = W2[(size_t)(k0 + 1) * 32 + n];
        float w10 = W2[(size_t)(k0 + 8) * 32 + n];
        float w11 = W2[(size_t)(k0 + 9) * 32 + n];
        W2p[r * 36 + n] = make_uint2(packh2(w00, w01), packh2(w10, w11));
    }
    if (tid < 128) b1s[tid] = BIAS ? b1[tid] : 0.0f;
    if (tid < 32)  b2s[tid] = BIAS ? b2[tid] : 0.0f;
    __syncthreads();

    const int w = tid >> 5, lane = tid & 31;
    const int g = lane >> 2, tig = lane & 3;
    const int slab = w >> 1, hh = w & 1;
    const int srow0 = slab * 16 + g, srow1 = srow0 + 8;

    for (int tile = t0; tile < t1; tile++) {
        const int base = tile * 64 + slab * 16;
        const int r0 = base + g, r1 = base + g + 8;
        const bool v0 = r0 < M, v1 = r1 < M;
        const float* A0 = A + (size_t)r0 * K;
        const float* A1 = A + (size_t)r1 * K;

        float acc1[8][4];
#pragma unroll
        for (int nt = 0; nt < 8; nt++)
#pragma unroll
            for (int j = 0; j < 4; j++) acc1[nt][j] = 0.0f;

        const float2 z2 = make_float2(0.f, 0.f);
#pragma unroll
        for (int h = 0; h < K / 64; h++) {
            uint32_t af[4][4];
#pragma unroll
            for (int q = 0; q < 4; q++) {
                const int kb = h * 64 + q * 16 + 2 * tig;
                float2 p00 = v0 ? *(const float2*)(A0 + kb)     : z2;
                float2 p01 = v0 ? *(const float2*)(A0 + kb + 8) : z2;
                float2 p10 = v1 ? *(const float2*)(A1 + kb)     : z2;
                float2 p11 = v1 ? *(const float2*)(A1 + kb + 8) : z2;
                af[q][0] = packh2(silu_f(p00.x), silu_f(p00.y));
                af[q][1] = packh2(silu_f(p10.x), silu_f(p10.y));
                af[q][2] = packh2(silu_f(p01.x), silu_f(p01.y));
                af[q][3] = packh2(silu_f(p11.x), silu_f(p11.y));
            }
#pragma unroll
            for (int q = 0; q < 4; q++) {
                const int kg = h * 4 + q;
                const int brow = (kg * 4 + tig) * 132;
#pragma unroll
                for (int nt = 0; nt < 8; nt++) {
                    const int col = hh * 64 + nt * 8 + g;
                    uint2 bb = W1p[brow + col];
                    mma_f16(acc1[nt], af[q][0], af[q][1], af[q][2], af[q][3],
                            bb.x, bb.y);
                }
            }
        }

#pragma unroll
        for (int nt = 0; nt < 8; nt++) {
            const int cA = hh * 64 + nt * 8 + 2 * tig;
            const int cp = hh * 32 + nt * 4 + tig;
            C1h[srow0 * 68 + cp] = packh2(silu_f(acc1[nt][0] + b1s[cA]),
                                          silu_f(acc1[nt][1] + b1s[cA + 1]));
            C1h[srow1 * 68 + cp] = packh2(silu_f(acc1[nt][2] + b1s[cA]),
                                          silu_f(acc1[nt][3] + b1s[cA + 1]));
        }
        __syncthreads();

        float acc2[2][4];
#pragma unroll
        for (int nt = 0; nt < 2; nt++)
#pragma unroll
            for (int j = 0; j < 4; j++) acc2[nt][j] = 0.0f;

#pragma unroll
        for (int kg = 0; kg < 8; kg++) {
            uint32_t a0 = C1h[srow0 * 68 + kg * 8 + tig];
            uint32_t a1 = C1h[srow1 * 68 + kg * 8 + tig];
            uint32_t a2 = C1h[srow0 * 68 + kg * 8 + tig + 4];
            uint32_t a3 = C1h[srow1 * 68 + kg * 8 + tig + 4];
            const int brow = (kg * 4 + tig) * 36;
#pragma unroll
            for (int nt = 0; nt < 2; nt++) {
                const int n = (hh * 2 + nt) * 8 + g;
                uint2 bb = W2p[brow + n];
                mma_f16(acc2[nt], a0, a1, a2, a3, bb.x, bb.y);
            }
        }

#pragma unroll
        for (int nt = 0; nt < 2; nt++) {
            const int cA = (hh * 2 + nt) * 8 + 2 * tig;
            if (v0) {
                Y[(size_t)r0 * 32 + cA]     = acc2[nt][0] + b2s[cA];
                Y[(size_t)r0 * 32 + cA + 1] = acc2[nt][1] + b2s[cA + 1];
            }
            if (v1) {
                Y[(size_t)r1 * 32 + cA]     = acc2[nt][2] + b2s[cA];
                Y[(size_t)r1 * 32 + cA + 1] = acc2[nt][3] + b2s[cA + 1];
            }
        }
        __syncthreads();
    }
}

// One launch: both MLPs + zero agg + zero src-histogram. 61 KB smem, 3 blocks/SM.
__global__ void __launch_bounds__(256, 3) mlp_all_kernel(
    const float* __restrict__ coeffs, const float* __restrict__ Wc1,
    const float* __restrict__ Wc2,
    const float* __restrict__ x, const float* __restrict__ W1,
    const float* __restrict__ b1, const float* __restrict__ W2,
    const float* __restrict__ b2,
    float* __restrict__ cbuf, float* __restrict__ hbuf,
    float4* __restrict__ aggz)
{
    extern __shared__ uint32_t sm[];

    const float4 z4 = make_float4(0.f, 0.f, 0.f, 0.f);
    for (int i = blockIdx.x * 256 + threadIdx.x; i < N_NODES * DDIM / 4;
         i += (NB_C + NB_N) * 256)
        aggz[i] = z4;
    for (int i = blockIdx.x * 256 + threadIdx.x; i < N_NODES;
         i += (NB_C + NB_N) * 256)
        g_cnt[i] = 0;

    if (blockIdx.x < NB_C) {
        const int bi = blockIdx.x;
        const int t0 = (int)((long long)bi * TILES_C / NB_C);
        const int t1 = (int)((long long)(bi + 1) * TILES_C / NB_C);
        mlp_tiles<CDIM, false>(coeffs, Wc1, nullptr, Wc2, nullptr, cbuf,
                               N_NODES * RDIM, t0, t1, sm);
    } else {
        const int bi = blockIdx.x - NB_C;
        const int t0 = (int)((long long)bi * TILES_N / NB_N);
        const int t1 = (int)((long long)(bi + 1) * TILES_N / NB_N);
        mlp_tiles<HDIM, true>(x, W1, b1, W2, b2, hbuf,
                              N_NODES, t0, t1, sm);
    }
}

// ---- counting sort by src ----
__global__ void hist_kernel(const int* __restrict__ ei) {
    int e = blockIdx.x * 256 + threadIdx.x;
    if (e < N_EDGES) atomicAdd(&g_cnt[ei[e]], 1);
}

// single-block exclusive scan of g_cnt -> g_off (1024 threads, shfl-based)
__global__ void __launch_bounds__(1024) scan_kernel() {
    __shared__ int wsum[32];
    __shared__ int carry;
    const int lane = threadIdx.x & 31, wid = threadIdx.x >> 5;
    if (threadIdx.x == 0) carry = 0;
    __syncthreads();
    for (int base = 0; base < N_NODES; base += 1024) {
        const int i = base + threadIdx.x;
        const int v = (i < N_NODES) ? g_cnt[i] : 0;
        int inc = v;
#pragma unroll
        for (int off = 1; off < 32; off <<= 1) {
            int t = __shfl_up_sync(0xffffffffu, inc, off);
            if (lane >= off) inc += t;
        }
        if (lane == 31) wsum[wid] = inc;
        __syncthreads();
        if (wid == 0) {
            int s = wsum[lane];
            int si = s;
#pragma unroll
            for (int off = 1; off < 32; off <<= 1) {
                int t = __shfl_up_sync(0xffffffffu, si, off);
                if (lane >= off) si += t;
            }
            wsum[lane] = si - s;   // exclusive warp offsets
        }
        __syncthreads();
        if (i < N_NODES) g_off[i] = carry + wsum[wid] + inc - v;
        __syncthreads();
        if (threadIdx.x == 1023) carry += wsum[31] + inc;  // chunk total
        __syncthreads();
    }
}

__global__ void scatter_kernel(const int* __restrict__ ei) {
    int e = blockIdx.x * 256 + threadIdx.x;
    if (e < N_EDGES) {
        int s = ei[e];
        int d = ei[N_EDGES + e];
        int pos = atomicAdd(&g_off[s], 1);
        g_src_s[pos] = s;
        g_dst_s[pos] = d;
        g_perm[pos] = e;
    }
}

// FFMA GEMM (final up-projection): Y[M,NC] = A[M,K]@W[K,NC]
template<int K, int NC, int TM, bool SILU, bool BIAS>
__global__ void __launch_bounds__((NC/4)*(TM/8)) gemm_silu_kernel(
    const float* __restrict__ A, const float* __restrict__ W,
    const float* __restrict__ bias, float* __restrict__ Y, int M)
{
    __shared__ float As[TM][33];
    __shared__ float Ws[32][NC];
    const int tx = threadIdx.x;
    const int ty = threadIdx.y;
    const int TH = (NC/4)*(TM/8);
    const int tid = ty*(NC/4) + tx;
    const int m0 = blockIdx.x * TM;

    float acc[8][4];
#pragma unroll
    for (int i = 0; i < 8; i++)
#pragma unroll
        for (int j = 0; j < 4; j++) acc[i][j] = 0.0f;

    for (int k0 = 0; k0 < K; k0 += 32) {
        for (int idx = tid; idx < TM*8; idx += TH) {
            int row = idx >> 3, cc = idx & 7;
            float4 v = make_float4(0.f, 0.f, 0.f, 0.f);
            int m = m0 + row;
            if (m < M && (k0 + cc*4) < K) v = *(const float4*)(A + (size_t)m * K + k0 + cc*4);
            if (SILU) { v.x = silu_f(v.x); v.y = silu_f(v.y); v.z = silu_f(v.z); v.w = silu_f(v.w); }
            As[row][cc*4+0] = v.x; As[row][cc*4+1] = v.y;
            As[row][cc*4+2] = v.z; As[row][cc*4+3] = v.w;
        }
        for (int idx = tid; idx < 8*NC; idx += TH) {
            int kk = idx / (NC/4), cc = idx % (NC/4);
            float4 wv = make_float4(0.f,0.f,0.f,0.f);
            if (k0 + kk < K) wv = *(const float4*)(W + (size_t)(k0+kk)*NC + cc*4);
            *(float4*)&Ws[kk][cc*4] = wv;
        }
        __syncthreads();
#pragma unroll 8
        for (int kk = 0; kk < 32; kk++) {
            float4 wv = *(const float4*)&Ws[kk][tx*4];
#pragma unroll
            for (int i = 0; i < 8; i++) {
                float a = As[ty*8+i][kk];
                acc[i][0] = fmaf(a, wv.x, acc[i][0]);
                acc[i][1] = fmaf(a, wv.y, acc[i][1]);
                acc[i][2] = fmaf(a, wv.z, acc[i][2]);
                acc[i][3] = fmaf(a, wv.w, acc[i][3]);
            }
        }
        __syncthreads();
    }

    float4 bv = make_float4(0.f, 0.f, 0.f, 0.f);
    if (BIAS) bv = *(const float4*)(bias + tx*4);
#pragma unroll
    for (int i = 0; i < 8; i++) {
        int m = m0 + ty*8 + i;
        if (m < M) {
            float4 o = make_float4(acc[i][0]+bv.x, acc[i][1]+bv.y,
                                   acc[i][2]+bv.z, acc[i][3]+bv.w);
            *(float4*)(Y + (size_t)m * NC + tx*4) = o;
        }
    }
}

// TWO edges per warp over SRC-SORTED edge list. src-side c rows repeat across
// consecutive warps -> L1 hits; agg reds hit same address -> cheap REDG.
__global__ void edge_kernel(const float* __restrict__ c, const float* __restrict__ h,
                            const float* __restrict__ rbfs, float* __restrict__ agg)
{
    int gwarp = blockIdx.x * 8 + (threadIdx.x >> 5);
    const int e0 = gwarp * 2;
    if (e0 >= N_EDGES) return;
    const int e1 = e0 + 1;
    const int lane = threadIdx.x & 31;
    const int grp = lane >> 3;          // rA = grp, rB = grp+4
    const int col4 = lane & 7;          // owns cols col4*4 .. col4*4+3

    const int src0 = g_src_s[e0], src1 = g_src_s[e1];
    const int dst0 = g_dst_s[e0], dst1 = g_dst_s[e1];
    const int p0 = g_perm[e0],    p1 = g_perm[e1];

    const float4* c4 = (const float4*)c;
    const size_t db0 = (size_t)dst0 * 64, sb0 = (size_t)src0 * 64;
    const size_t db1 = (size_t)dst1 * 64, sb1 = (size_t)src1 * 64;

    // issue ALL gathers up-front (8 independent LDG.128 per lane)
    float4 d00 = c4[db0 + lane], d01 = c4[db0 + 32 + lane];
    float4 s00 = c4[sb0 + lane], s01 = c4[sb0 + 32 + lane];
    float4 d10 = c4[db1 + lane], d11 = c4[db1 + 32 + lane];
    float4 s10 = c4[sb1 + lane], s11 = c4[sb1 + 32 + lane];

    // rbf rows via perm (two 32B gathers in one instruction)
    float rv = 0.0f;
    if (lane < 8)        rv = rbfs[(size_t)p0 * RDIM + lane];
    else if (lane < 16)  rv = rbfs[(size_t)p1 * RDIM + (lane - 8)];

#pragma unroll
    for (int e = 0; e < 2; e++) {
        float4 da  = (e == 0) ? d00 : d10;
        float4 dbv = (e == 0) ? d01 : d11;
        float4 sa  = (e == 0) ? s00 : s10;
        float4 sbv = (e == 0) ? s01 : s11;

        float ceA[4], ceB[4];
        ceA[0] = da.x * (sa.x + 1.0f);   ceA[1] = da.y * (sa.y + 1.0f);
        ceA[2] = da.z * (sa.z + 1.0f);   ceA[3] = da.w * (sa.w + 1.0f);
        ceB[0] = dbv.x * (sbv.x + 1.0f); ceB[1] = dbv.y * (sbv.y + 1.0f);
        ceB[2] = dbv.z * (sbv.z + 1.0f); ceB[3] = dbv.w * (sbv.w + 1.0f);

        float ssA = 0.f, ssB = 0.f;
#pragma unroll
        for (int j = 0; j < 4; j++) { ssA = fmaf(ceA[j], ceA[j], ssA); ssB = fmaf(ceB[j], ceB[j], ssB); }
#pragma unroll
        for (int mask = 1; mask <= 4; mask <<= 1) {
            ssA += __shfl_xor_sync(0xffffffffu, ssA, mask);
            ssB += __shfl_xor_sync(0xffffffffu, ssB, mask);
        }
        float invA = rsqrtf(fmaxf(ssA, 1e-24f));
        float invB = rsqrtf(fmaxf(ssB, 1e-24f));

        float rbA = __shfl_sync(0xffffffffu, rv, e * 8 + grp);
        float rbB = __shfl_sync(0xffffffffu, rv, e * 8 + grp + 4);

        float sA = rbA * invA, sB = rbB * invB;
        float wl[4];
#pragma unroll
        for (int j = 0; j < 4; j++) wl[j] = ceA[j] * sA + ceB[j] * sB;
#pragma unroll
        for (int mask = 8; mask <= 16; mask <<= 1)
#pragma unroll
            for (int j = 0; j < 4; j++) wl[j] += __shfl_xor_sync(0xffffffffu, wl[j], mask);

        float sq = 0.f;
#pragma unroll
        for (int j = 0; j < 4; j++) sq = fmaf(wl[j], wl[j], sq);
#pragma unroll
        for (int mask = 1; mask <= 4; mask <<= 1)
            sq += __shfl_xor_sync(0xffffffffu, sq, mask);
        float invw = rsqrtf(fmaxf(sq, 1e-24f));

        if (grp == 0) {
            const int dste = (e == 0) ? dst0 : dst1;
            const int srce = (e == 0) ? src0 : src1;
            const float4 hv = *(const float4*)(h + (size_t)dste * DDIM + col4 * 4);
            float4 m = make_float4(hv.x * wl[0] * invw, hv.y * wl[1] * invw,
                                   hv.z * wl[2] * invw, hv.w * wl[3] * invw);
            red_v4(agg + (size_t)srce * DDIM + col4 * 4, m);
        }
    }
}

extern "C" void kernel_launch(void* const* d_in, const int* in_sizes, int n_in,
                              void* d_out, int out_size)
{
    const float* x      = (const float*)d_in[0];
    const float* rbfs   = (const float*)d_in[1];
    const float* coeffs = (const float*)d_in[2];
    const float* W1     = (const float*)d_in[3];
    const float* b1     = (const float*)d_in[4];
    const float* W2     = (const float*)d_in[5];
    const float* b2     = (const float*)d_in[6];
    const float* Wc1    = (const float*)d_in[7];
    const float* Wc2    = (const float*)d_in[8];
    const float* Wu     = (const float*)d_in[9];
    const int*   ei     = (const int*)d_in[10];
    float* out = (float*)d_out;

    float *hbuf, *cbuf, *agg;
    cudaGetSymbolAddress((void**)&hbuf, g_hbuf);
    cudaGetSymbolAddress((void**)&cbuf, g_cbuf);
    cudaGetSymbolAddress((void**)&agg,  g_agg);

    // smem (node max): (32*132 + 32*36) uint2 *8B + 64*68*4 + 160*4 = 61056 B
    const int smem_mlp = (32 * 132 + 32 * 36) * 8 + 64 * 68 * 4 + 160 * 4;
    cudaFuncSetAttribute(mlp_all_kernel,
                         cudaFuncAttributeMaxDynamicSharedMemorySize, smem_mlp);

    // both MLPs + agg/counter zeroing in one launch, 3 blocks/SM
    mlp_all_kernel<<<NB_C + NB_N, 256, smem_mlp>>>(
        coeffs, Wc1, Wc2, x, W1, b1, W2, b2, cbuf, hbuf, (float4*)agg);

    // counting sort of edges by src
    hist_kernel<<<(N_EDGES + 255) / 256, 256>>>(ei);
    scan_kernel<<<1, 1024>>>();
    scatter_kernel<<<(N_EDGES + 255) / 256, 256>>>(ei);

    // edge stage on sorted edges: 2 edges/warp + v4 reductions into agg
    edge_kernel<<<N_EDGES / 16, 256>>>(cbuf, hbuf, rbfs, agg);

    // out = agg @ Wu
    gemm_silu_kernel<32,128,64,false,false>
        <<<(N_NODES + 63)/64, dim3(32,8)>>>(agg, Wu, nullptr, out, N_NODES);
}

// round 16
// speedup vs baseline: 1.0078x; 1.0078x over previous
#include <cuda_runtime.h>
#include <cuda_fp16.h>
#include <cstdint>

#define N_NODES 50000
#define N_EDGES 800000
#define HDIM 128
#define DDIM 32
#define CDIM 64
#define RDIM 8

#define TILES_C 6250            // ceil(400000/64)
#define TILES_N 782             // ceil(50000/64)
#define NB_C 366
#define NB_N 78                 // 444 = 3 blocks/SM

#define SCAN_B 512
#define NBLK_SCAN ((N_NODES + SCAN_B - 1) / SCAN_B)   // 98

// ---- scratch (device globals; no allocation in kernel_launch) ----
__device__ float g_hbuf[N_NODES * DDIM];        // h          [N,32]
__device__ float g_cbuf[N_NODES * RDIM * DDIM]; // c          [N*R,32]
__device__ float g_agg[N_NODES * DDIM];         // segsum     [N,32]
__device__ int   g_cnt[N_NODES];                // src histogram
__device__ int   g_rowptr[N_NODES + 1];         // CSR row pointers
__device__ int   g_off[N_NODES];                // scatter cursors
__device__ int   g_bsum[NBLK_SCAN];             // scan block partials
__device__ int   g_dst_s[N_EDGES];              // dst, sorted by src
__device__ int   g_perm[N_EDGES];               // original edge id, sorted by src

__device__ __forceinline__ float silu_f(float v) {
    return __fdividef(v, 1.0f + __expf(-v));
}

__device__ __forceinline__ uint32_t packh2(float lo, float hi) {
    uint32_t r;
    asm("cvt.rn.f16x2.f32 %0, %1, %2;" : "=r"(r) : "f"(hi), "f"(lo));
    return r;
}

__device__ __forceinline__ void mma_f16(float d[4], uint32_t a0, uint32_t a1,
                                        uint32_t a2, uint32_t a3,
                                        uint32_t b0, uint32_t b1) {
    asm volatile(
        "mma.sync.aligned.m16n8k16.row.col.f32.f16.f16.f32 "
        "{%0,%1,%2,%3},{%4,%5,%6,%7},{%8,%9},{%0,%1,%2,%3};"
        : "+f"(d[0]), "+f"(d[1]), "+f"(d[2]), "+f"(d[3])
        : "r"(a0), "r"(a1), "r"(a2), "r"(a3), "r"(b0), "r"(b1));
}

// Fused 2-layer MLP (fp16 tensor-core) — unchanged from R14.
template<int K, bool BIAS>
__device__ void mlp_tiles(const float* __restrict__ A, const float* __restrict__ W1,
                          const float* __restrict__ b1, const float* __restrict__ W2,
                          const float* __restrict__ b2, float* __restrict__ Y,
                          int M, int t0, int t1, uint32_t* sm)
{
    constexpr int R1 = K / 4;
    uint2* W1p = (uint2*)sm;                    // [R1][132]
    uint2* W2p = W1p + R1 * 132;                // [32][36]
    uint32_t* C1h = (uint32_t*)(W2p + 32 * 36); // [64][68]
    float* b1s = (float*)(C1h + 64 * 68);       // [128]
    float* b2s = b1s + 128;                     // [32]

    const int tid = threadIdx.x;

    for (int i = tid; i < R1 * 128; i += 256) {
        int r = i >> 7, col = i & 127;
        int kg = r >> 2, tg = r & 3;
        int k0 = kg * 16 + 2 * tg;
        float w00 = W1[(size_t)k0 * 128 + col];
        float w01 = W1[(size_t)(k0 + 1) * 128 + col];
        float w10 = W1[(size_t)(k0 + 8) * 128 + col];
        float w11 = W1[(size_t)(k0 + 9) * 128 + col];
        W1p[r * 132 + col] = make_uint2(packh2(w00, w01), packh2(w10, w11));
    }
    for (int i = tid; i < 32 * 32; i += 256) {
        int r = i >> 5, n = i & 31;
        int kg = r >> 2, tg = r & 3;
        int k0 = kg * 16 + 2 * tg;
        float w00 = W2[(size_t)k0 * 32 + n];
        float w01 = W2[(size_t)(k0 + 1) * 32 + n];
        float w10 = W2[(size_t)(k0 + 8) * 32 + n];
        float w11 = W2[(size_t)(k0 + 9) * 32 + n];
        W2p[r * 36 + n] = make_uint2(packh2(w00, w01), packh2(w10, w11));
    }
    if (tid < 128) b1s[tid] = BIAS ? b1[tid] : 0.0f;
    if (tid < 32)  b2s[tid] = BIAS ? b2[tid] : 0.0f;
    __syncthreads();

    const int w = tid >> 5, lane = tid & 31;
    const int g = lane >> 2, tig = lane & 3;
    const int slab = w >> 1, hh = w & 1;
    const int srow0 = slab * 16 + g, srow1 = srow0 + 8;

    for (int tile = t0; tile < t1; tile++) {
        const int base = tile * 64 + slab * 16;
        const int r0 = base + g, r1 = base + g + 8;
        const bool v0 = r0 < M, v1 = r1 < M;
        const float* A0 = A + (size_t)r0 * K;
        const float* A1 = A + (size_t)r1 * K;

        float acc1[8][4];
#pragma unroll
        for (int nt = 0; nt < 8; nt++)
#pragma unroll
            for (int j = 0; j < 4; j++) acc1[nt][j] = 0.0f;

        const float2 z2 = make_float2(0.f, 0.f);
#pragma unroll
        for (int h = 0; h < K / 64; h++) {
            uint32_t af[4][4];
#pragma unroll
            for (int q = 0; q < 4; q++) {
                const int kb = h * 64 + q * 16 + 2 * tig;
                float2 p00 = v0 ? *(const float2*)(A0 + kb)     : z2;
                float2 p01 = v0 ? *(const float2*)(A0 + kb + 8) : z2;
                float2 p10 = v1 ? *(const float2*)(A1 + kb)     : z2;
                float2 p11 = v1 ? *(const float2*)(A1 + kb + 8) : z2;
                af[q][0] = packh2(silu_f(p00.x), silu_f(p00.y));
                af[q][1] = packh2(silu_f(p10.x), silu_f(p10.y));
                af[q][2] = packh2(silu_f(p01.x), silu_f(p01.y));
                af[q][3] = packh2(silu_f(p11.x), silu_f(p11.y));
            }
#pragma unroll
            for (int q = 0; q < 4; q++) {
                const int kg = h * 4 + q;
                const int brow = (kg * 4 + tig) * 132;
#pragma unroll
                for (int nt = 0; nt < 8; nt++) {
                    const int col = hh * 64 + nt * 8 + g;
                    uint2 bb = W1p[brow + col];
                    mma_f16(acc1[nt], af[q][0], af[q][1], af[q][2], af[q][3],
                            bb.x, bb.y);
                }
            }
        }

#pragma unroll
        for (int nt = 0; nt < 8; nt++) {
            const int cA = hh * 64 + nt * 8 + 2 * tig;
            const int cp = hh * 32 + nt * 4 + tig;
            C1h[srow0 * 68 + cp] = packh2(silu_f(acc1[nt][0] + b1s[cA]),
                                          silu_f(acc1[nt][1] + b1s[cA + 1]));
            C1h[srow1 * 68 + cp] = packh2(silu_f(acc1[nt][2] + b1s[cA]),
                                          silu_f(acc1[nt][3] + b1s[cA + 1]));
        }
        __syncthreads();

        float acc2[2][4];
#pragma unroll
        for (int nt = 0; nt < 2; nt++)
#pragma unroll
            for (int j = 0; j < 4; j++) acc2[nt][j] = 0.0f;

#pragma unroll
        for (int kg = 0; kg < 8; kg++) {
            uint32_t a0 = C1h[srow0 * 68 + kg * 8 + tig];
            uint32_t a1 = C1h[srow1 * 68 + kg * 8 + tig];
            uint32_t a2 = C1h[srow0 * 68 + kg * 8 + tig + 4];
            uint32_t a3 = C1h[srow1 * 68 + kg * 8 + tig + 4];
            const int brow = (kg * 4 + tig) * 36;
#pragma unroll
            for (int nt = 0; nt < 2; nt++) {
                const int n = (hh * 2 + nt) * 8 + g;
                uint2 bb = W2p[brow + n];
                mma_f16(acc2[nt], a0, a1, a2, a3, bb.x, bb.y);
            }
        }

#pragma unroll
        for (int nt = 0; nt < 2; nt++) {
            const int cA = (hh * 2 + nt) * 8 + 2 * tig;
            if (v0) {
                Y[(size_t)r0 * 32 + cA]     = acc2[nt][0] + b2s[cA];
                Y[(size_t)r0 * 32 + cA + 1] = acc2[nt][1] + b2s[cA + 1];
            }
            if (v1) {
                Y[(size_t)r1 * 32 + cA]     = acc2[nt][2] + b2s[cA];
                Y[(size_t)r1 * 32 + cA + 1] = acc2[nt][3] + b2s[cA + 1];
            }
        }
        __syncthreads();
    }
}

// One launch: both MLPs + zero src-histogram (agg no longer needs zeroing —
// the CSR edge kernel fully writes it). 61 KB smem, 3 blocks/SM.
__global__ void __launch_bounds__(256, 3) mlp_all_kernel(
    const float* __restrict__ coeffs, const float* __restrict__ Wc1,
    const float* __restrict__ Wc2,
    const float* __restrict__ x, const float* __restrict__ W1,
    const float* __restrict__ b1, const float* __restrict__ W2,
    const float* __restrict__ b2,
    float* __restrict__ cbuf, float* __restrict__ hbuf)
{
    extern __shared__ uint32_t sm[];

    for (int i = blockIdx.x * 256 + threadIdx.x; i < N_NODES;
         i += (NB_C + NB_N) * 256)
        g_cnt[i] = 0;

    if (blockIdx.x < NB_C) {
        const int bi = blockIdx.x;
        const int t0 = (int)((long long)bi * TILES_C / NB_C);
        const int t1 = (int)((long long)(bi + 1) * TILES_C / NB_C);
        mlp_tiles<CDIM, false>(coeffs, Wc1, nullptr, Wc2, nullptr, cbuf,
                               N_NODES * RDIM, t0, t1, sm);
    } else {
        const int bi = blockIdx.x - NB_C;
        const int t0 = (int)((long long)bi * TILES_N / NB_N);
        const int t1 = (int)((long long)(bi + 1) * TILES_N / NB_N);
        mlp_tiles<HDIM, true>(x, W1, b1, W2, b2, hbuf,
                              N_NODES, t0, t1, sm);
    }
}

// ---- counting sort by src (multi-block scan) ----
__global__ void hist_kernel(const int* __restrict__ ei) {
    int e = blockIdx.x * 256 + threadIdx.x;
    if (e < N_EDGES) atomicAdd(&g_cnt[ei[e]], 1);
}

// phase 1: per-block exclusive scan of 512 counts; block totals to g_bsum
__global__ void __launch_bounds__(SCAN_B) scan1_kernel() {
    __shared__ int wsum[SCAN_B / 32];
    const int i = blockIdx.x * SCAN_B + threadIdx.x;
    const int lane = threadIdx.x & 31, wid = threadIdx.x >> 5;
    const int v = (i < N_NODES) ? g_cnt[i] : 0;
    int inc = v;
#pragma unroll
    for (int off = 1; off < 32; off <<= 1) {
        int t = __shfl_up_sync(0xffffffffu, inc, off);
        if (lane >= off) inc += t;
    }
    if (lane == 31) wsum[wid] = inc;
    __syncthreads();
    if (wid == 0) {
        int s = (lane < SCAN_B / 32) ? wsum[lane] : 0;
        int si = s;
#pragma unroll
        for (int off = 1; off < SCAN_B / 32; off <<= 1) {
            int t = __shfl_up_sync(0xffffffffu, si, off);
            if (lane >= off) si += t;
        }
        if (lane < SCAN_B / 32) wsum[lane] = si - s;
    }
    __syncthreads();
    if (i < N_NODES) g_rowptr[i] = wsum[wid] + inc - v;
    if (threadIdx.x == SCAN_B - 1) g_bsum[blockIdx.x] = wsum[wid] + inc;
}

// phase 2: exclusive scan of the 98 block totals (tiny, serial in 1 thread)
__global__ void scan2_kernel() {
    __shared__ int sh[NBLK_SCAN];
    if (threadIdx.x < NBLK_SCAN) sh[threadIdx.x] = g_bsum[threadIdx.x];
    __syncthreads();
    if (threadIdx.x == 0) {
        int run = 0;
        for (int k = 0; k < NBLK_SCAN; k++) { int t = sh[k]; sh[k] = run; run += t; }
    }
    __syncthreads();
    if (threadIdx.x < NBLK_SCAN) g_bsum[threadIdx.x] = sh[threadIdx.x];
}

// phase 3: add block offsets; produce rowptr (stable) and off (scatter cursor)
__global__ void scan3_kernel() {
    int i = blockIdx.x * 256 + threadIdx.x;
    if (i < N_NODES) {
        int off = g_rowptr[i] + g_bsum[i / SCAN_B];
        g_rowptr[i] = off;
        g_off[i] = off;
    }
    if (i == 0) g_rowptr[N_NODES] = N_EDGES;
}

__global__ void scatter_kernel(const int* __restrict__ ei) {
    int e = blockIdx.x * 256 + threadIdx.x;
    if (e < N_EDGES) {
        int s = ei[e];
        int pos = atomicAdd(&g_off[s], 1);
        g_dst_s[pos] = ei[N_EDGES + e];
        g_perm[pos] = e;
    }
}

// FFMA GEMM (final up-projection): Y[M,NC] = A[M,K]@W[K,NC]
template<int K, int NC, int TM, bool SILU, bool BIAS>
__global__ void __launch_bounds__((NC/4)*(TM/8)) gemm_silu_kernel(
    const float* __restrict__ A, const float* __restrict__ W,
    const float* __restrict__ bias, float* __restrict__ Y, int M)
{
    __shared__ float As[TM][33];
    __shared__ float Ws[32][NC];
    const int tx = threadIdx.x;
    const int ty = threadIdx.y;
    const int TH = (NC/4)*(TM/8);
    const int tid = ty*(NC/4) + tx;
    const int m0 = blockIdx.x * TM;

    float acc[8][4];
#pragma unroll
    for (int i = 0; i < 8; i++)
#pragma unroll
        for (int j = 0; j < 4; j++) acc[i][j] = 0.0f;

    for (int k0 = 0; k0 < K; k0 += 32) {
        for (int idx = tid; idx < TM*8; idx += TH) {
            int row = idx >> 3, cc = idx & 7;
            float4 v = make_float4(0.f, 0.f, 0.f, 0.f);
            int m = m0 + row;
            if (m < M && (k0 + cc*4) < K) v = *(const float4*)(A + (size_t)m * K + k0 + cc*4);
            if (SILU) { v.x = silu_f(v.x); v.y = silu_f(v.y); v.z = silu_f(v.z); v.w = silu_f(v.w); }
            As[row][cc*4+0] = v.x; As[row][cc*4+1] = v.y;
            As[row][cc*4+2] = v.z; As[row][cc*4+3] = v.w;
        }
        for (int idx = tid; idx < 8*NC; idx += TH) {
            int kk = idx / (NC/4), cc = idx % (NC/4);
            float4 wv = make_float4(0.f,0.f,0.f,0.f);
            if (k0 + kk < K) wv = *(const float4*)(W + (size_t)(k0+kk)*NC + cc*4);
            *(float4*)&Ws[kk][cc*4] = wv;
        }
        __syncthreads();
#pragma unroll 8
        for (int kk = 0; kk < 32; kk++) {
            float4 wv = *(const float4*)&Ws[kk][tx*4];
#pragma unroll
            for (int i = 0; i < 8; i++) {
                float a = As[ty*8+i][kk];
                acc[i][0] = fmaf(a, wv.x, acc[i][0]);
                acc[i][1] = fmaf(a, wv.y, acc[i][1]);
                acc[i][2] = fmaf(a, wv.z, acc[i][2]);
                acc[i][3] = fmaf(a, wv.w, acc[i][3]);
            }
        }
        __syncthreads();
    }

    float4 bv = make_float4(0.f, 0.f, 0.f, 0.f);
    if (BIAS) bv = *(const float4*)(bias + tx*4);
#pragma unroll
    for (int i = 0; i < 8; i++) {
        int m = m0 + ty*8 + i;
        if (m < M) {
            float4 o = make_float4(acc[i][0]+bv.x, acc[i][1]+bv.y,
                                   acc[i][2]+bv.z, acc[i][3]+bv.w);
            *(float4*)(Y + (size_t)m * NC + tx*4) = o;
        }
    }
}

// CSR edge kernel: ONE WARP PER SRC NODE. c[src] lives in registers for the
// whole edge list; per edge only c[dst] (1KB), h[dst] (128B), rbf row (32B)
// are loaded. Output accumulated in registers -> one coalesced 128B store.
// No atomics, no agg zeroing. Next dst row double-buffered.
__global__ void edge_csr_kernel(const float* __restrict__ c, const float* __restrict__ h,
                                const float* __restrict__ rbfs, float* __restrict__ agg)
{
    const int src = blockIdx.x * 8 + (threadIdx.x >> 5);
    if (src >= N_NODES) return;
    const int lane = threadIdx.x & 31;
    const int grp = lane >> 3;          // rA = grp, rB = grp+4
    const int col4 = lane & 7;          // owns cols col4*4 .. col4*4+3

    const int beg = g_rowptr[src];
    const int end = g_rowptr[src + 1];

    const float4* c4 = (const float4*)c;
    const size_t sb = (size_t)src * 64;
    const float4 s0 = c4[sb + lane], s1 = c4[sb + 32 + lane];
    const float spA[4] = { s0.x + 1.0f, s0.y + 1.0f, s0.z + 1.0f, s0.w + 1.0f };
    const float spB[4] = { s1.x + 1.0f, s1.y + 1.0f, s1.z + 1.0f, s1.w + 1.0f };

    float acc[4] = { 0.f, 0.f, 0.f, 0.f };

    int e = beg;
    int ndst = 0, np = 0;
    float4 nd0, nd1;
    if (e < end) {
        ndst = __ldg(&g_dst_s[e]);
        np   = __ldg(&g_perm[e]);
        nd0 = c4[(size_t)ndst * 64 + lane];
        nd1 = c4[(size_t)ndst * 64 + 32 + lane];
    }

    while (e < end) {
        const int dst = ndst, p = np;
        const float4 d0 = nd0, d1 = nd1;

        // rbf row + h row for current edge (issued early, consumed late)
        float rv = (lane < 8) ? __ldg(&rbfs[(size_t)p * RDIM + lane]) : 0.0f;
        float4 hv = make_float4(0.f, 0.f, 0.f, 0.f);
        if (grp == 0) hv = *(const float4*)(h + (size_t)dst * DDIM + col4 * 4);

        // prefetch next edge's dst row
        e++;
        if (e < end) {
            ndst = __ldg(&g_dst_s[e]);
            np   = __ldg(&g_perm[e]);
            nd0 = c4[(size_t)ndst * 64 + lane];
            nd1 = c4[(size_t)ndst * 64 + 32 + lane];
        }

        float ceA[4], ceB[4];
        ceA[0] = d0.x * spA[0]; ceA[1] = d0.y * spA[1];
        ceA[2] = d0.z * spA[2]; ceA[3] = d0.w * spA[3];
        ceB[0] = d1.x * spB[0]; ceB[1] = d1.y * spB[1];
        ceB[2] = d1.z * spB[2]; ceB[3] = d1.w * spB[3];

        float ssA = 0.f, ssB = 0.f;
#pragma unroll
        for (int j = 0; j < 4; j++) { ssA = fmaf(ceA[j], ceA[j], ssA); ssB = fmaf(ceB[j], ceB[j], ssB); }
#pragma unroll
        for (int mask = 1; mask <= 4; mask <<= 1) {
            ssA += __shfl_xor_sync(0xffffffffu, ssA, mask);
            ssB += __shfl_xor_sync(0xffffffffu, ssB, mask);
        }
        const float invA = rsqrtf(fmaxf(ssA, 1e-24f));
        const float invB = rsqrtf(fmaxf(ssB, 1e-24f));

        const float rbA = __shfl_sync(0xffffffffu, rv, grp);
        const float rbB = __shfl_sync(0xffffffffu, rv, grp + 4);

        const float sA = rbA * invA, sB = rbB * invB;
        float wl[4];
#pragma unroll
        for (int j = 0; j < 4; j++) wl[j] = ceA[j] * sA + ceB[j] * sB;
#pragma unroll
        for (int mask = 8; mask <= 16; mask <<= 1)
#pragma unroll
            for (int j = 0; j < 4; j++) wl[j] += __shfl_xor_sync(0xffffffffu, wl[j], mask);

        float sq = 0.f;
#pragma unroll
        for (int j = 0; j < 4; j++) sq = fmaf(wl[j], wl[j], sq);
#pragma unroll
        for (int mask = 1; mask <= 4; mask <<= 1)
            sq += __shfl_xor_sync(0xffffffffu, sq, mask);
        const float invw = rsqrtf(fmaxf(sq, 1e-24f));

        if (grp == 0) {
            acc[0] = fmaf(hv.x, wl[0] * invw, acc[0]);
            acc[1] = fmaf(hv.y, wl[1] * invw, acc[1]);
            acc[2] = fmaf(hv.z, wl[2] * invw, acc[2]);
            acc[3] = fmaf(hv.w, wl[3] * invw, acc[3]);
        }
    }

    if (grp == 0)
        *(float4*)(agg + (size_t)src * DDIM + col4 * 4) =
            make_float4(acc[0], acc[1], acc[2], acc[3]);
}

extern "C" void kernel_launch(void* const* d_in, const int* in_sizes, int n_in,
                              void* d_out, int out_size)
{
    const float* x      = (const float*)d_in[0];
    const float* rbfs   = (const float*)d_in[1];
    const float* coeffs = (const float*)d_in[2];
    const float* W1     = (const float*)d_in[3];
    const float* b1     = (const float*)d_in[4];
    const float* W2     = (const float*)d_in[5];
    const float* b2     = (const float*)d_in[6];
    const float* Wc1    = (const float*)d_in[7];
    const float* Wc2    = (const float*)d_in[8];
    const float* Wu     = (const float*)d_in[9];
    const int*   ei     = (const int*)d_in[10];
    float* out = (float*)d_out;

    float *hbuf, *cbuf, *agg;
    cudaGetSymbolAddress((void**)&hbuf, g_hbuf);
    cudaGetSymbolAddress((void**)&cbuf, g_cbuf);
    cudaGetSymbolAddress((void**)&agg,  g_agg);

    // smem (node max): (32*132 + 32*36) uint2 *8B + 64*68*4 + 160*4 = 61056 B
    const int smem_mlp = (32 * 132 + 32 * 36) * 8 + 64 * 68 * 4 + 160 * 4;
    cudaFuncSetAttribute(mlp_all_kernel,
                         cudaFuncAttributeMaxDynamicSharedMemorySize, smem_mlp);

    // both MLPs + cnt zeroing in one launch, 3 blocks/SM
    mlp_all_kernel<<<NB_C + NB_N, 256, smem_mlp>>>(
        coeffs, Wc1, Wc2, x, W1, b1, W2, b2, cbuf, hbuf);

    // counting sort of edges by src (multi-block scan)
    hist_kernel<<<(N_EDGES + 255) / 256, 256>>>(ei);
    scan1_kernel<<<NBLK_SCAN, SCAN_B>>>();
    scan2_kernel<<<1, 128>>>();
    scan3_kernel<<<(N_NODES + 255) / 256, 256>>>();
    scatter_kernel<<<(N_EDGES + 255) / 256, 256>>>(ei);

    // CSR edge stage: warp per src, register-resident src row, no atomics
    edge_csr_kernel<<<(N_NODES + 7) / 8, 256>>>(cbuf, hbuf, rbfs, agg);

    // out = agg @ Wu
    gemm_silu_kernel<32,128,64,false,false>
        <<<(N_NODES + 63)/64, dim3(32,8)>>>(agg, Wu, nullptr, out, N_NODES);
}

// round 17
// speedup vs baseline: 1.0798x; 1.0714x over previous
#include <cuda_runtime.h>
#include <cuda_fp16.h>
#include <cstdint>

#define N_NODES 50000
#define N_EDGES 800000
#define HDIM 128
#define DDIM 32
#define CDIM 64
#define RDIM 8

#define TILES_C 6250            // ceil(400000/64)
#define TILES_N 782             // ceil(50000/64)
#define NB_C 366
#define NB_N 78                 // 444 = 3 blocks/SM; node tile ~1.7x coeffs tile

// ---- scratch (device globals; no allocation in kernel_launch) ----
__device__ float g_hbuf[N_NODES * DDIM];        // h          [N,32]
__device__ float g_cbuf[N_NODES * RDIM * DDIM]; // c          [N*R,32]
__device__ float g_agg[N_NODES * DDIM];         // segsum     [N,32]

__device__ __forceinline__ float silu_f(float v) {
    return __fdividef(v, 1.0f + __expf(-v));
}

__device__ __forceinline__ uint32_t packh2(float lo, float hi) {
    uint32_t r;
    asm("cvt.rn.f16x2.f32 %0, %1, %2;" : "=r"(r) : "f"(hi), "f"(lo));
    return r;
}

__device__ __forceinline__ void mma_f16(float d[4], uint32_t a0, uint32_t a1,
                                        uint32_t a2, uint32_t a3,
                                        uint32_t b0, uint32_t b1) {
    asm volatile(
        "mma.sync.aligned.m16n8k16.row.col.f32.f16.f16.f32 "
        "{%0,%1,%2,%3},{%4,%5,%6,%7},{%8,%9},{%0,%1,%2,%3};"
        : "+f"(d[0]), "+f"(d[1]), "+f"(d[2]), "+f"(d[3])
        : "r"(a0), "r"(a1), "r"(a2), "r"(a3), "r"(b0), "r"(b1));
}

__device__ __forceinline__ void red_v4(float* p, float4 v) {
    asm volatile("red.global.add.v4.f32 [%0], {%1,%2,%3,%4};"
                 :: "l"(p), "f"(v.x), "f"(v.y), "f"(v.z), "f"(v.w) : "memory");
}

// Fused 2-layer MLP (fp16 tensor-core) — unchanged from R14.
template<int K, bool BIAS>
__device__ void mlp_tiles(const float* __restrict__ A, const float* __restrict__ W1,
                          const float* __restrict__ b1, const float* __restrict__ W2,
                          const float* __restrict__ b2, float* __restrict__ Y,
                          int M, int t0, int t1, uint32_t* sm)
{
    constexpr int R1 = K / 4;
    uint2* W1p = (uint2*)sm;                    // [R1][132]
    uint2* W2p = W1p + R1 * 132;                // [32][36]
    uint32_t* C1h = (uint32_t*)(W2p + 32 * 36); // [64][68]
    float* b1s = (float*)(C1h + 64 * 68);       // [128]
    float* b2s = b1s + 128;                     // [32]

    const int tid = threadIdx.x;

    for (int i = tid; i < R1 * 128; i += 256) {
        int r = i >> 7, col = i & 127;
        int kg = r >> 2, tg = r & 3;
        int k0 = kg * 16 + 2 * tg;
        float w00 = W1[(size_t)k0 * 128 + col];
        float w01 = W1[(size_t)(k0 + 1) * 128 + col];
        float w10 = W1[(size_t)(k0 + 8) * 128 + col];
        float w11 = W1[(size_t)(k0 + 9) * 128 + col];
        W1p[r * 132 + col] = make_uint2(packh2(w00, w01), packh2(w10, w11));
    }
    for (int i = tid; i < 32 * 32; i += 256) {
        int r = i >> 5, n = i & 31;
        int kg = r >> 2, tg = r & 3;
        int k0 = kg * 16 + 2 * tg;
        float w00 = W2[(size_t)k0 * 32 + n];
        float w01 = W2[(size_t)(k0 + 1) * 32 + n];
        float w10 = W2[(size_t)(k0 + 8) * 32 + n];
        float w11 = W2[(size_t)(k0 + 9) * 32 + n];
        W2p[r * 36 + n] = make_uint2(packh2(w00, w01), packh2(w10, w11));
    }
    if (tid < 128) b1s[tid] = BIAS ? b1[tid] : 0.0f;
    if (tid < 32)  b2s[tid] = BIAS ? b2[tid] : 0.0f;
    __syncthreads();

    const int w = tid >> 5, lane = tid & 31;
    const int g = lane >> 2, tig = lane & 3;
    const int slab = w >> 1, hh = w & 1;
    const int srow0 = slab * 16 + g, srow1 = srow0 + 8;

    for (int tile = t0; tile < t1; tile++) {
        const int base = tile * 64 + slab * 16;
        const int r0 = base + g, r1 = base + g + 8;
        const bool v0 = r0 < M, v1 = r1 < M;
        const float* A0 = A + (size_t)r0 * K;
        const float* A1 = A + (size_t)r1 * K;

        float acc1[8][4];
#pragma unroll
        for (int nt = 0; nt < 8; nt++)
#pragma unroll
            for (int j = 0; j < 4; j++) acc1[nt][j] = 0.0f;

        const float2 z2 = make_float2(0.f, 0.f);
#pragma unroll
        for (int h = 0; h < K / 64; h++) {
            uint32_t af[4][4];
#pragma unroll
            for (int q = 0; q < 4; q++) {
                const int kb = h * 64 + q * 16 + 2 * tig;
                float2 p00 = v0 ? *(const float2*)(A0 + kb)     : z2;
                float2 p01 = v0 ? *(const float2*)(A0 + kb + 8) : z2;
                float2 p10 = v1 ? *(const float2*)(A1 + kb)     : z2;
                float2 p11 = v1 ? *(const float2*)(A1 + kb + 8) : z2;
                af[q][0] = packh2(silu_f(p00.x), silu_f(p00.y));
                af[q][1] = packh2(silu_f(p10.x), silu_f(p10.y));
                af[q][2] = packh2(silu_f(p01.x), silu_f(p01.y));
                af[q][3] = packh2(silu_f(p11.x), silu_f(p11.y));
            }
#pragma unroll
            for (int q = 0; q < 4; q++) {
                const int kg = h * 4 + q;
                const int brow = (kg * 4 + tig) * 132;
#pragma unroll
                for (int nt = 0; nt < 8; nt++) {
                    const int col = hh * 64 + nt * 8 + g;
                    uint2 bb = W1p[brow + col];
                    mma_f16(acc1[nt], af[q][0], af[q][1], af[q][2], af[q][3],
                            bb.x, bb.y);
                }
            }
        }

#pragma unroll
        for (int nt = 0; nt < 8; nt++) {
            const int cA = hh * 64 + nt * 8 + 2 * tig;
            const int cp = hh * 32 + nt * 4 + tig;
            C1h[srow0 * 68 + cp] = packh2(silu_f(acc1[nt][0] + b1s[cA]),
                                          silu_f(acc1[nt][1] + b1s[cA + 1]));
            C1h[srow1 * 68 + cp] = packh2(silu_f(acc1[nt][2] + b1s[cA]),
                                          silu_f(acc1[nt][3] + b1s[cA + 1]));
        }
        __syncthreads();

        float acc2[2][4];
#pragma unroll
        for (int nt = 0; nt < 2; nt++)
#pragma unroll
            for (int j = 0; j < 4; j++) acc2[nt][j] = 0.0f;

#pragma unroll
        for (int kg = 0; kg < 8; kg++) {
            uint32_t a0 = C1h[srow0 * 68 + kg * 8 + tig];
            uint32_t a1 = C1h[srow1 * 68 + kg * 8 + tig];
            uint32_t a2 = C1h[srow0 * 68 + kg * 8 + tig + 4];
            uint32_t a3 = C1h[srow1 * 68 + kg * 8 + tig + 4];
            const int brow = (kg * 4 + tig) * 36;
#pragma unroll
            for (int nt = 0; nt < 2; nt++) {
                const int n = (hh * 2 + nt) * 8 + g;
                uint2 bb = W2p[brow + n];
                mma_f16(acc2[nt], a0, a1, a2, a3, bb.x, bb.y);
            }
        }

#pragma unroll
        for (int nt = 0; nt < 2; nt++) {
            const int cA = (hh * 2 + nt) * 8 + 2 * tig;
            if (v0) {
                Y[(size_t)r0 * 32 + cA]     = acc2[nt][0] + b2s[cA];
                Y[(size_t)r0 * 32 + cA + 1] = acc2[nt][1] + b2s[cA + 1];
            }
            if (v1) {
                Y[(size_t)r1 * 32 + cA]     = acc2[nt][2] + b2s[cA];
                Y[(size_t)r1 * 32 + cA + 1] = acc2[nt][3] + b2s[cA + 1];
            }
        }
        __syncthreads();
    }
}

// One launch: both MLPs + zero agg. 61 KB smem, 3 blocks/SM.
__global__ void __launch_bounds__(256, 3) mlp_all_kernel(
    const float* __restrict__ coeffs, const float* __restrict__ Wc1,
    const float* __restrict__ Wc2,
    const float* __restrict__ x, const float* __restrict__ W1,
    const float* __restrict__ b1, const float* __restrict__ W2,
    const float* __restrict__ b2,
    float* __restrict__ cbuf, float* __restrict__ hbuf,
    float4* __restrict__ aggz)
{
    extern __shared__ uint32_t sm[];

    const float4 z4 = make_float4(0.f, 0.f, 0.f, 0.f);
    for (int i = blockIdx.x * 256 + threadIdx.x; i < N_NODES * DDIM / 4;
         i += (NB_C + NB_N) * 256)
        aggz[i] = z4;

    if (blockIdx.x < NB_C) {
        const int bi = blockIdx.x;
        const int t0 = (int)((long long)bi * TILES_C / NB_C);
        const int t1 = (int)((long long)(bi + 1) * TILES_C / NB_C);
        mlp_tiles<CDIM, false>(coeffs, Wc1, nullptr, Wc2, nullptr, cbuf,
                               N_NODES * RDIM, t0, t1, sm);
    } else {
        const int bi = blockIdx.x - NB_C;
        const int t0 = (int)((long long)bi * TILES_N / NB_N);
        const int t1 = (int)((long long)(bi + 1) * TILES_N / NB_N);
        mlp_tiles<HDIM, true>(x, W1, b1, W2, b2, hbuf,
                              N_NODES, t0, t1, sm);
    }
}

// FFMA GEMM (final up-projection): Y[M,NC] = A[M,K]@W[K,NC]
template<int K, int NC, int TM, bool SILU, bool BIAS, int MINB>
__global__ void __launch_bounds__((NC/4)*(TM/8), MINB) gemm_silu_kernel(
    const float* __restrict__ A, const float* __restrict__ W,
    const float* __restrict__ bias, float* __restrict__ Y, int M)
{
    __shared__ float As[TM][33];
    __shared__ float Ws[32][NC];
    const int tx = threadIdx.x;
    const int ty = threadIdx.y;
    const int TH = (NC/4)*(TM/8);
    const int tid = ty*(NC/4) + tx;
    const int m0 = blockIdx.x * TM;

    float acc[8][4];
#pragma unroll
    for (int i = 0; i < 8; i++)
#pragma unroll
        for (int j = 0; j < 4; j++) acc[i][j] = 0.0f;

    for (int k0 = 0; k0 < K; k0 += 32) {
        for (int idx = tid; idx < TM*8; idx += TH) {
            int row = idx >> 3, cc = idx & 7;
            float4 v = make_float4(0.f, 0.f, 0.f, 0.f);
            int m = m0 + row;
            if (m < M && (k0 + cc*4) < K) v = *(const float4*)(A + (size_t)m * K + k0 + cc*4);
            if (SILU) { v.x = silu_f(v.x); v.y = silu_f(v.y); v.z = silu_f(v.z); v.w = silu_f(v.w); }
            As[row][cc*4+0] = v.x; As[row][cc*4+1] = v.y;
            As[row][cc*4+2] = v.z; As[row][cc*4+3] = v.w;
        }
        for (int idx = tid; idx < 8*NC; idx += TH) {
            int kk = idx / (NC/4), cc = idx % (NC/4);
            float4 wv = make_float4(0.f,0.f,0.f,0.f);
            if (k0 + kk < K) wv = *(const float4*)(W + (size_t)(k0+kk)*NC + cc*4);
            *(float4*)&Ws[kk][cc*4] = wv;
        }
        __syncthreads();
#pragma unroll 8
        for (int kk = 0; kk < 32; kk++) {
            float4 wv = *(const float4*)&Ws[kk][tx*4];
#pragma unroll
            for (int i = 0; i < 8; i++) {
                float a = As[ty*8+i][kk];
                acc[i][0] = fmaf(a, wv.x, acc[i][0]);
                acc[i][1] = fmaf(a, wv.y, acc[i][1]);
                acc[i][2] = fmaf(a, wv.z, acc[i][2]);
                acc[i][3] = fmaf(a, wv.w, acc[i][3]);
            }
        }
        __syncthreads();
    }

    float4 bv = make_float4(0.f, 0.f, 0.f, 0.f);
    if (BIAS) bv = *(const float4*)(bias + tx*4);
#pragma unroll
    for (int i = 0; i < 8; i++) {
        int m = m0 + ty*8 + i;
        if (m < M) {
            float4 o = make_float4(acc[i][0]+bv.x, acc[i][1]+bv.y,
                                   acc[i][2]+bv.z, acc[i][3]+bv.w);
            *(float4*)(Y + (size_t)m * NC + tx*4) = o;
        }
    }
}

// TWO edges per warp, coalesced fp32 c loads; h rows hoisted to the gather
// phase so their latency overlaps the shuffle chain.
__global__ void edge_kernel(const float* __restrict__ c, const float* __restrict__ h,
                            const float* __restrict__ rbfs, const int* __restrict__ ei,
                            float* __restrict__ agg)
{
    int gwarp = blockIdx.x * 8 + (threadIdx.x >> 5);
    const int e0 = gwarp * 2;
    if (e0 >= N_EDGES) return;
    const int e1 = e0 + 1;
    const int lane = threadIdx.x & 31;
    const int grp = lane >> 3;          // rA = grp, rB = grp+4
    const int col4 = lane & 7;          // owns cols col4*4 .. col4*4+3

    const int src0 = ei[e0],           src1 = ei[e1];
    const int dst0 = ei[N_EDGES + e0], dst1 = ei[N_EDGES + e1];

    const float4* c4 = (const float4*)c;
    const size_t db0 = (size_t)dst0 * 64, sb0 = (size_t)src0 * 64;
    const size_t db1 = (size_t)dst1 * 64, sb1 = (size_t)src1 * 64;

    // issue ALL gathers up-front (8 c LDG.128 + 2 h LDG.128 per warp)
    float4 d00 = c4[db0 + lane], d01 = c4[db0 + 32 + lane];
    float4 s00 = c4[sb0 + lane], s01 = c4[sb0 + 32 + lane];
    float4 d10 = c4[db1 + lane], d11 = c4[db1 + 32 + lane];
    float4 s10 = c4[sb1 + lane], s11 = c4[sb1 + 32 + lane];

    float4 hv0 = make_float4(0.f, 0.f, 0.f, 0.f), hv1 = hv0;
    if (grp == 0) {
        hv0 = *(const float4*)(h + (size_t)dst0 * DDIM + col4 * 4);
        hv1 = *(const float4*)(h + (size_t)dst1 * DDIM + col4 * 4);
    }

    // one coalesced rbf load covers both edges (rows e0,e1 are contiguous)
    float rv = (lane < 16) ? rbfs[(size_t)e0 * RDIM + lane] : 0.0f;

#pragma unroll
    for (int e = 0; e < 2; e++) {
        float4 da  = (e == 0) ? d00 : d10;
        float4 dbv = (e == 0) ? d01 : d11;
        float4 sa  = (e == 0) ? s00 : s10;
        float4 sbv = (e == 0) ? s01 : s11;

        float ceA[4], ceB[4];
        ceA[0] = da.x * (sa.x + 1.0f);   ceA[1] = da.y * (sa.y + 1.0f);
        ceA[2] = da.z * (sa.z + 1.0f);   ceA[3] = da.w * (sa.w + 1.0f);
        ceB[0] = dbv.x * (sbv.x + 1.0f); ceB[1] = dbv.y * (sbv.y + 1.0f);
        ceB[2] = dbv.z * (sbv.z + 1.0f); ceB[3] = dbv.w * (sbv.w + 1.0f);

        float ssA = 0.f, ssB = 0.f;
#pragma unroll
        for (int j = 0; j < 4; j++) { ssA = fmaf(ceA[j], ceA[j], ssA); ssB = fmaf(ceB[j], ceB[j], ssB); }
#pragma unroll
        for (int mask = 1; mask <= 4; mask <<= 1) {
            ssA += __shfl_xor_sync(0xffffffffu, ssA, mask);
            ssB += __shfl_xor_sync(0xffffffffu, ssB, mask);
        }
        float invA = rsqrtf(fmaxf(ssA, 1e-24f));
        float invB = rsqrtf(fmaxf(ssB, 1e-24f));

        float rbA = __shfl_sync(0xffffffffu, rv, e * 8 + grp);
        float rbB = __shfl_sync(0xffffffffu, rv, e * 8 + grp + 4);

        float sA = rbA * invA, sB = rbB * invB;
        float wl[4];
#pragma unroll
        for (int j = 0; j < 4; j++) wl[j] = ceA[j] * sA + ceB[j] * sB;
#pragma unroll
        for (int mask = 8; mask <= 16; mask <<= 1)
#pragma unroll
            for (int j = 0; j < 4; j++) wl[j] += __shfl_xor_sync(0xffffffffu, wl[j], mask);

        float sq = 0.f;
#pragma unroll
        for (int j = 0; j < 4; j++) sq = fmaf(wl[j], wl[j], sq);
#pragma unroll
        for (int mask = 1; mask <= 4; mask <<= 1)
            sq += __shfl_xor_sync(0xffffffffu, sq, mask);
        float invw = rsqrtf(fmaxf(sq, 1e-24f));

        if (grp == 0) {
            const int srce = (e == 0) ? src0 : src1;
            const float4 hv = (e == 0) ? hv0 : hv1;
            float4 m = make_float4(hv.x * wl[0] * invw, hv.y * wl[1] * invw,
                                   hv.z * wl[2] * invw, hv.w * wl[3] * invw);
            red_v4(agg + (size_t)srce * DDIM + col4 * 4, m);
        }
    }
}

extern "C" void kernel_launch(void* const* d_in, const int* in_sizes, int n_in,
                              void* d_out, int out_size)
{
    const float* x      = (const float*)d_in[0];
    const float* rbfs   = (const float*)d_in[1];
    const float* coeffs = (const float*)d_in[2];
    const float* W1     = (const float*)d_in[3];
    const float* b1     = (const float*)d_in[4];
    const float* W2     = (const float*)d_in[5];
    const float* b2     = (const float*)d_in[6];
    const float* Wc1    = (const float*)d_in[7];
    const float* Wc2    = (const float*)d_in[8];
    const float* Wu     = (const float*)d_in[9];
    const int*   ei     = (const int*)d_in[10];
    float* out = (float*)d_out;

    float *hbuf, *cbuf, *agg;
    cudaGetSymbolAddress((void**)&hbuf, g_hbuf);
    cudaGetSymbolAddress((void**)&cbuf, g_cbuf);
    cudaGetSymbolAddress((void**)&agg,  g_agg);

    // smem (node max): (32*132 + 32*36) uint2 *8B + 64*68*4 + 160*4 = 61056 B
    const int smem_mlp = (32 * 132 + 32 * 36) * 8 + 64 * 68 * 4 + 160 * 4;
    cudaFuncSetAttribute(mlp_all_kernel,
                         cudaFuncAttributeMaxDynamicSharedMemorySize, smem_mlp);

    // both MLPs + agg zeroing in one launch, 3 blocks/SM
    mlp_all_kernel<<<NB_C + NB_N, 256, smem_mlp>>>(
        coeffs, Wc1, Wc2, x, W1, b1, W2, b2, cbuf, hbuf, (float4*)agg);

    // edge stage: 2 edges per warp + v4 reduction segment-sum into agg
    edge_kernel<<<N_EDGES/16, 256>>>(cbuf, hbuf, rbfs, ei, agg);

    // out = agg @ Wu  (TM=128, 512 threads, 2 blocks/SM)
    gemm_silu_kernel<32,128,128,false,false,2>
        <<<(N_NODES + 127)/128, dim3(32,16)>>>(agg, Wu, nullptr, out, N_NODES);
}